// round 12
// baseline (speedup 1.0000x reference)
#include <cuda_runtime.h>
#include <math.h>

#define BB      2
#define SS      2048
#define INDIM   1024
#define QH_     16
#define KVH_    4
#define HD_     64
#define G_      4
#define NKV     256
#define QSCALE  0.180336879f   // 0.125 * log2(e)
#define NSPLIT  8

__device__ float g_Wqs[INDIM * NKV];          // folded + scaled + tf32
__device__ float g_Wk[INDIM * NKV];           // tf32
__device__ float g_Wv[INDIM * NKV];           // tf32
__device__ float g_Wo[NKV * INDIM];           // tf32
__device__ float g_Q[BB * KVH_ * SS * HD_];   // tf32, pre-scaled
__device__ float g_K[BB * KVH_ * SS * HD_];   // tf32
__device__ float g_V[BB * KVH_ * SS * HD_];   // tf32
__device__ float g_AO[BB * SS * NKV];         // tf32 (merge output)
__device__ float  g_Op[BB * KVH_ * SS * NSPLIT * HD_];
__device__ float2 g_Ml[BB * KVH_ * SS * NSPLIT];

// --------------------------- helpers --------------------------------------
__device__ __forceinline__ unsigned f2tf(float f) {
    unsigned r;
    asm("cvt.rna.tf32.f32 %0, %1;" : "=r"(r) : "f"(f));
    return r;
}
__device__ __forceinline__ float ex2f(float x) {
    float y;
    asm("ex2.approx.f32 %0, %1;" : "=f"(y) : "f"(x));
    return y;
}
__device__ __forceinline__ void mma_tf32(float (&d)[4], const unsigned (&a)[4],
                                         const unsigned (&b)[2]) {
    asm volatile(
        "mma.sync.aligned.m16n8k8.row.col.f32.tf32.tf32.f32 "
        "{%0,%1,%2,%3}, {%4,%5,%6,%7}, {%8,%9}, {%0,%1,%2,%3};"
        : "+f"(d[0]), "+f"(d[1]), "+f"(d[2]), "+f"(d[3])
        : "r"(a[0]), "r"(a[1]), "r"(a[2]), "r"(a[3]), "r"(b[0]), "r"(b[1]));
}
__device__ __forceinline__ void cpa16(void* dst, const void* src) {
    unsigned d = (unsigned)__cvta_generic_to_shared(dst);
    asm volatile("cp.async.cg.shared.global [%0], [%1], 16;" :: "r"(d), "l"(src) : "memory");
}
#define CP_COMMIT() asm volatile("cp.async.commit_group;" ::: "memory")
#define CP_WAIT0()  asm volatile("cp.async.wait_group 0;" ::: "memory")
#define CP_WAIT1()  asm volatile("cp.async.wait_group 1;" ::: "memory")

// ---------------------------------------------------------------------------
// Fused prep: y=0 folds Wq (group-sum, scale, tf32); y=1 rounds Wk/Wv/Wo.
// ---------------------------------------------------------------------------
__global__ void prep_kernel(const float* __restrict__ Wq,
                            const float* __restrict__ Wk,
                            const float* __restrict__ Wv,
                            const float* __restrict__ Wo) {
    int idx = blockIdx.x * blockDim.x + threadIdx.x;
    if (blockIdx.y == 0) {
        if (idx >= INDIM * NKV) return;
        int i = idx >> 8;
        int n = idx & 255;
        int h = n >> 6, d = n & 63;
        const float* p = Wq + (size_t)i * (QH_ * HD_) + (size_t)(h * G_) * HD_ + d;
        g_Wqs[idx] = __uint_as_float(
            f2tf(QSCALE * (p[0] + p[HD_] + p[2 * HD_] + p[3 * HD_])));
    } else {
        const int Q4 = (INDIM * NKV) / 4;
        if (idx >= 3 * Q4) return;
        int which = idx / Q4;
        int off = (idx - which * Q4) * 4;
        const float* src = (which == 0) ? Wk : ((which == 1) ? Wv : Wo);
        float* dst = (which == 0) ? g_Wk : ((which == 1) ? g_Wv : g_Wo);
        float4 v = *(const float4*)(src + off);
        v.x = __uint_as_float(f2tf(v.x));
        v.y = __uint_as_float(f2tf(v.y));
        v.z = __uint_as_float(f2tf(v.z));
        v.w = __uint_as_float(f2tf(v.w));
        *(float4*)(dst + off) = v;
    }
}

// ---------------------------------------------------------------------------
// tf32 GEMM, block tile 128x128 (halves L2 traffic vs 128x64).
// 256 thr = 8 warps (2m x 4n), warp tile 64x32, BK=16, 2-stage cp.async.
// A [m][k] pitch 20, B [k][n] pitch 136 (same conflict-free structure).
// B pre-rounded tf32; A converted iff CVT_A.
// ---------------------------------------------------------------------------
template<int KD, int N, bool SCATTER, bool CVT_A>
__device__ __forceinline__ void gemm_body(
        const float* __restrict__ A, const float* __restrict__ Bm,
        float* __restrict__ C) {
    __shared__ float As[2][128][20];
    __shared__ float Bs[2][16][136];

    int tid = threadIdx.x;
    int w = tid >> 5, lane = tid & 31, g = lane >> 2, qd = lane & 3;
    int wm = w & 1, wn = w >> 1;
    int m0 = blockIdx.y * 128, n0 = blockIdx.x * 128;

    // loaders: A: 2 thr/row, 2 chunks; B: 512 float4 chunks -> 2 per thread
    int ar = tid >> 1, ac = (tid & 1) * 8;
    int br0 = tid >> 5, bc0 = (tid & 31) * 4;          // chunk tid
    int br1 = (tid + 256) >> 5, bc1 = (tid & 31) * 4;  // chunk tid+256
    const float* ApG = A + (size_t)(m0 + ar) * KD + ac;
    const float* BpG0 = Bm + (size_t)br0 * N + n0 + bc0;
    const float* BpG1 = Bm + (size_t)br1 * N + n0 + bc1;

    float acc[4][4][4];
    #pragma unroll
    for (int mt = 0; mt < 4; mt++)
        #pragma unroll
        for (int nt = 0; nt < 4; nt++)
            #pragma unroll
            for (int e = 0; e < 4; e++) acc[mt][nt][e] = 0.f;

    cpa16(&As[0][ar][ac],     ApG);
    cpa16(&As[0][ar][ac + 4], ApG + 4);
    cpa16(&Bs[0][br0][bc0],   BpG0);
    cpa16(&Bs[0][br1][bc1],   BpG1);
    CP_COMMIT();

    const int KT = KD / 16;
    int buf = 0;
    #pragma unroll 1
    for (int t = 0; t < KT; t++) {
        if (t + 1 < KT) {
            int k0 = (t + 1) * 16;
            cpa16(&As[buf ^ 1][ar][ac],     ApG + k0);
            cpa16(&As[buf ^ 1][ar][ac + 4], ApG + k0 + 4);
            cpa16(&Bs[buf ^ 1][br0][bc0],   BpG0 + (size_t)k0 * N);
            cpa16(&Bs[buf ^ 1][br1][bc1],   BpG1 + (size_t)k0 * N);
            CP_COMMIT();
            CP_WAIT1();
        } else {
            CP_WAIT0();
        }
        __syncthreads();

        #pragma unroll
        for (int ks = 0; ks < 2; ks++) {
            int kb = ks * 8;
            unsigned af[4][4];
            #pragma unroll
            for (int mt = 0; mt < 4; mt++) {
                int row = wm * 64 + mt * 16 + g;
                if (CVT_A) {
                    af[mt][0] = f2tf(As[buf][row][kb + qd]);
                    af[mt][1] = f2tf(As[buf][row + 8][kb + qd]);
                    af[mt][2] = f2tf(As[buf][row][kb + qd + 4]);
                    af[mt][3] = f2tf(As[buf][row + 8][kb + qd + 4]);
                } else {
                    af[mt][0] = __float_as_uint(As[buf][row][kb + qd]);
                    af[mt][1] = __float_as_uint(As[buf][row + 8][kb + qd]);
                    af[mt][2] = __float_as_uint(As[buf][row][kb + qd + 4]);
                    af[mt][3] = __float_as_uint(As[buf][row + 8][kb + qd + 4]);
                }
            }
            unsigned bf[4][2];
            #pragma unroll
            for (int nt = 0; nt < 4; nt++) {
                int col = wn * 32 + nt * 8 + g;
                bf[nt][0] = __float_as_uint(Bs[buf][kb + qd][col]);
                bf[nt][1] = __float_as_uint(Bs[buf][kb + qd + 4][col]);
            }
            #pragma unroll
            for (int mt = 0; mt < 4; mt++)
                #pragma unroll
                for (int nt = 0; nt < 4; nt++)
                    mma_tf32(acc[mt][nt], af[mt], bf[nt]);
        }
        __syncthreads();
        buf ^= 1;
    }

    #pragma unroll
    for (int mt = 0; mt < 4; mt++) {
        #pragma unroll
        for (int nt = 0; nt < 4; nt++) {
            int row = m0 + wm * 64 + mt * 16 + g;
            int col = n0 + wn * 32 + nt * 8 + 2 * qd;
            if (SCATTER) {
                float2 lo = make_float2(__uint_as_float(f2tf(acc[mt][nt][0])),
                                        __uint_as_float(f2tf(acc[mt][nt][1])));
                float2 hi = make_float2(__uint_as_float(f2tf(acc[mt][nt][2])),
                                        __uint_as_float(f2tf(acc[mt][nt][3])));
                int b = row >> 11, s = row & 2047;
                int h = col >> 6, d = col & 63;
                size_t base = (((size_t)(b * KVH_ + h) * SS) << 6) + (size_t)d;
                *(float2*)&C[base + ((size_t)s << 6)]       = lo;
                *(float2*)&C[base + ((size_t)(s + 8) << 6)] = hi;
            } else {
                *(float2*)&C[(size_t)row * N + col] =
                    make_float2(acc[mt][nt][0], acc[mt][nt][1]);
                *(float2*)&C[(size_t)(row + 8) * N + col] =
                    make_float2(acc[mt][nt][2], acc[mt][nt][3]);
            }
        }
    }
}

__global__ void __launch_bounds__(256) qkv_gemm_kernel(
        const float* __restrict__ q_in, const float* __restrict__ kv_in,
        float* __restrict__ Q, float* __restrict__ K, float* __restrict__ V) {
    int z = blockIdx.z;
    const float* A  = (z == 0) ? q_in : kv_in;
    const float* Bm = (z == 0) ? g_Wqs : ((z == 1) ? g_Wk : g_Wv);
    float* C        = (z == 0) ? Q : ((z == 1) ? K : V);
    gemm_body<INDIM, NKV, true, true>(A, Bm, C);
}

__global__ void __launch_bounds__(256) out_gemm_kernel(
        const float* __restrict__ A, float* __restrict__ C) {
    gemm_body<NKV, INDIM, false, false>(A, g_Wo, C);
}

// ---------------------------------------------------------------------------
// Causal flash attention, split-KV partials, NSPLIT=8 (verified).
// ---------------------------------------------------------------------------
#define KP 68
#define VP 72
#define ATTN_SMEM ((2 * 64 * KP + 2 * 64 * VP) * 4)

__global__ void __launch_bounds__(128, 3) attn_part_kernel() {
    extern __shared__ unsigned smp[];
    unsigned* Kb0 = smp;
    unsigned* Kb1 = Kb0 + 64 * KP;
    unsigned* Vb0 = Kb1 + 64 * KP;
    unsigned* Vb1 = Vb0 + 64 * VP;

    int bh = blockIdx.y;
    int qidx = blockIdx.x / NSPLIT;
    int split = blockIdx.x % NSPLIT;
    int qt = (SS / 64 - 1) - qidx;
    int q0 = qt * 64;
    int nseg = qt + 1;
    int lo = (split * nseg) / NSPLIT;
    int hi = ((split + 1) * nseg) / NSPLIT;

    const float* Qh = g_Q + (size_t)bh * SS * HD_;
    const float* Kh = g_K + (size_t)bh * SS * HD_;
    const float* Vh = g_V + (size_t)bh * SS * HD_;

    int tid = threadIdx.x;
    int w = tid >> 5, lane = tid & 31, g = lane >> 2, qd = lane & 3;
    int r0 = w * 16 + g;
    int lr = tid >> 4, lc = tid & 15;

    int sl0 = (lane & 28) | (qd >> 1);
    int sl1 = sl0 + 2;
    bool odd = (qd & 1) != 0;

    float m0 = -3.0e38f, m1 = -3.0e38f, l0 = 0.f, l1 = 0.f;
    float oacc[8][4];
    #pragma unroll
    for (int dt = 0; dt < 8; dt++)
        #pragma unroll
        for (int e = 0; e < 4; e++) oacc[dt][e] = 0.f;

    unsigned qf[8][4];

    if (lo < hi) {
        {
            const uint4* Qsrc = (const uint4*)(Qh + (size_t)q0 * 64);
            #pragma unroll
            for (int it = 0; it < 8; it++) {
                int r = lr + it * 8;
                *(uint4*)&Kb0[r * KP + lc * 4] = Qsrc[r * 16 + lc];
            }
        }
        __syncthreads();
        #pragma unroll
        for (int ks = 0; ks < 8; ks++) {
            qf[ks][0] = Kb0[r0 * KP + ks * 8 + qd];
            qf[ks][1] = Kb0[(r0 + 8) * KP + ks * 8 + qd];
            qf[ks][2] = Kb0[r0 * KP + ks * 8 + qd + 4];
            qf[ks][3] = Kb0[(r0 + 8) * KP + ks * 8 + qd + 4];
        }
        __syncthreads();

        {
            unsigned* Kn = (lo & 1) ? Kb1 : Kb0;
            unsigned* Vn = (lo & 1) ? Vb1 : Vb0;
            const float* Ksrc = Kh + (size_t)lo * 4096;
            const float* Vsrc = Vh + (size_t)lo * 4096;
            #pragma unroll
            for (int it = 0; it < 8; it++) {
                int r = lr + it * 8;
                cpa16(&Kn[r * KP + lc * 4], Ksrc + r * 64 + lc * 4);
                cpa16(&Vn[r * VP + lc * 4], Vsrc + r * 64 + lc * 4);
            }
        }
        CP_COMMIT();

        #pragma unroll 1
        for (int kt = lo; kt < hi; kt++) {
            unsigned* Kc = (kt & 1) ? Kb1 : Kb0;
            unsigned* Vc = (kt & 1) ? Vb1 : Vb0;
            if (kt + 1 < hi) {
                unsigned* Kn = (kt & 1) ? Kb0 : Kb1;
                unsigned* Vn = (kt & 1) ? Vb0 : Vb1;
                const float* Ksrc = Kh + (size_t)(kt + 1) * 4096;
                const float* Vsrc = Vh + (size_t)(kt + 1) * 4096;
                #pragma unroll
                for (int it = 0; it < 8; it++) {
                    int r = lr + it * 8;
                    cpa16(&Kn[r * KP + lc * 4], Ksrc + r * 64 + lc * 4);
                    cpa16(&Vn[r * VP + lc * 4], Vsrc + r * 64 + lc * 4);
                }
                CP_COMMIT();
                CP_WAIT1();
            } else {
                CP_WAIT0();
            }
            __syncthreads();

            float sacc[8][4];
            #pragma unroll
            for (int nt = 0; nt < 8; nt++)
                #pragma unroll
                for (int e = 0; e < 4; e++) sacc[nt][e] = 0.f;
            #pragma unroll
            for (int nt = 0; nt < 8; nt++) {
                #pragma unroll
                for (int ks = 0; ks < 8; ks++) {
                    unsigned kb[2];
                    kb[0] = Kc[(nt * 8 + g) * KP + ks * 8 + qd];
                    kb[1] = Kc[(nt * 8 + g) * KP + ks * 8 + qd + 4];
                    mma_tf32(sacc[nt], qf[ks], kb);
                }
            }

            if (kt == qt) {
                int grow0 = q0 + r0;
                #pragma unroll
                for (int nt = 0; nt < 8; nt++) {
                    int col = kt * 64 + nt * 8 + 2 * qd;
                    if (col     > grow0)     sacc[nt][0] = -1.0e30f;
                    if (col + 1 > grow0)     sacc[nt][1] = -1.0e30f;
                    if (col     > grow0 + 8) sacc[nt][2] = -1.0e30f;
                    if (col + 1 > grow0 + 8) sacc[nt][3] = -1.0e30f;
                }
            }

            float mx0 = -3.0e38f, mx1 = -3.0e38f;
            #pragma unroll
            for (int nt = 0; nt < 8; nt++) {
                mx0 = fmaxf(mx0, fmaxf(sacc[nt][0], sacc[nt][1]));
                mx1 = fmaxf(mx1, fmaxf(sacc[nt][2], sacc[nt][3]));
            }
            mx0 = fmaxf(mx0, __shfl_xor_sync(0xffffffffu, mx0, 1));
            mx0 = fmaxf(mx0, __shfl_xor_sync(0xffffffffu, mx0, 2));
            mx1 = fmaxf(mx1, __shfl_xor_sync(0xffffffffu, mx1, 1));
            mx1 = fmaxf(mx1, __shfl_xor_sync(0xffffffffu, mx1, 2));
            float mn0 = fmaxf(m0, mx0), mn1 = fmaxf(m1, mx1);
            float c0 = ex2f(m0 - mn0), c1 = ex2f(m1 - mn1);
            m0 = mn0; m1 = mn1;
            float rs0 = 0.f, rs1 = 0.f;
            #pragma unroll
            for (int nt = 0; nt < 8; nt++) {
                float p0 = ex2f(sacc[nt][0] - mn0);
                float p1 = ex2f(sacc[nt][1] - mn0);
                float p2 = ex2f(sacc[nt][2] - mn1);
                float p3 = ex2f(sacc[nt][3] - mn1);
                sacc[nt][0] = p0; sacc[nt][1] = p1;
                sacc[nt][2] = p2; sacc[nt][3] = p3;
                rs0 += p0 + p1; rs1 += p2 + p3;
            }
            rs0 += __shfl_xor_sync(0xffffffffu, rs0, 1);
            rs0 += __shfl_xor_sync(0xffffffffu, rs0, 2);
            rs1 += __shfl_xor_sync(0xffffffffu, rs1, 1);
            rs1 += __shfl_xor_sync(0xffffffffu, rs1, 2);
            l0 = l0 * c0 + rs0;
            l1 = l1 * c1 + rs1;
            #pragma unroll
            for (int dt = 0; dt < 8; dt++) {
                oacc[dt][0] *= c0; oacc[dt][1] *= c0;
                oacc[dt][2] *= c1; oacc[dt][3] *= c1;
            }

            unsigned pa[8][4];
            #pragma unroll
            for (int ks = 0; ks < 8; ks++) {
                float a0 = __shfl_sync(0xffffffffu, sacc[ks][0], sl0);
                float a1 = __shfl_sync(0xffffffffu, sacc[ks][1], sl0);
                float b0 = __shfl_sync(0xffffffffu, sacc[ks][2], sl0);
                float b1 = __shfl_sync(0xffffffffu, sacc[ks][3], sl0);
                float e0 = __shfl_sync(0xffffffffu, sacc[ks][0], sl1);
                float e1 = __shfl_sync(0xffffffffu, sacc[ks][1], sl1);
                float f0 = __shfl_sync(0xffffffffu, sacc[ks][2], sl1);
                float f1 = __shfl_sync(0xffffffffu, sacc[ks][3], sl1);
                pa[ks][0] = f2tf(odd ? a1 : a0);
                pa[ks][1] = f2tf(odd ? b1 : b0);
                pa[ks][2] = f2tf(odd ? e1 : e0);
                pa[ks][3] = f2tf(odd ? f1 : f0);
            }

            #pragma unroll
            for (int dt = 0; dt < 8; dt++) {
                #pragma unroll
                for (int ks = 0; ks < 8; ks++) {
                    unsigned vb[2];
                    vb[0] = Vc[(ks * 8 + qd) * VP + dt * 8 + g];
                    vb[1] = Vc[(ks * 8 + qd + 4) * VP + dt * 8 + g];
                    mma_tf32(oacc[dt], pa[ks], vb);
                }
            }
            __syncthreads();
        }
    }

    int grow = q0 + r0;
    size_t rid0 = ((size_t)bh * SS + grow) * NSPLIT + split;
    size_t rid1 = ((size_t)bh * SS + grow + 8) * NSPLIT + split;
    #pragma unroll
    for (int dt = 0; dt < 8; dt++) {
        int d = dt * 8 + 2 * qd;
        *(float2*)&g_Op[(rid0 << 6) + d] = make_float2(oacc[dt][0], oacc[dt][1]);
        *(float2*)&g_Op[(rid1 << 6) + d] = make_float2(oacc[dt][2], oacc[dt][3]);
    }
    if (qd == 0) {
        g_Ml[rid0] = make_float2(m0, l0);
        g_Ml[rid1] = make_float2(m1, l1);
    }
}

// ---------------------------------------------------------------------------
// Merge partials; emits tf32-rounded g_AO so out_gemm skips all cvts.
// ---------------------------------------------------------------------------
__global__ void __launch_bounds__(256) attn_merge_kernel() {
    int gr = blockIdx.x * 8 + (threadIdx.x >> 5);
    int lane = threadIdx.x & 31;
    int bh = gr >> 11;
    int row = gr & 2047;
    int b = bh >> 2, h = bh & 3;

    float2 ml[NSPLIT];
    #pragma unroll
    for (int s = 0; s < NSPLIT; s++) ml[s] = g_Ml[(size_t)gr * NSPLIT + s];
    float mmax = -3.0e38f;
    #pragma unroll
    for (int s = 0; s < NSPLIT; s++) mmax = fmaxf(mmax, ml[s].x);
    float ws[NSPLIT];
    float lt = 0.f;
    #pragma unroll
    for (int s = 0; s < NSPLIT; s++) {
        ws[s] = ex2f(ml[s].x - mmax);
        lt += ml[s].y * ws[s];
    }
    float inv = 1.0f / lt;

    int d = lane * 2;
    float a0 = 0.f, a1 = 0.f;
    #pragma unroll
    for (int s = 0; s < NSPLIT; s++) {
        float2 o = *(const float2*)&g_Op[((((size_t)gr * NSPLIT) + s) << 6) + d];
        a0 += o.x * ws[s];
        a1 += o.y * ws[s];
    }
    size_t base = (((size_t)b * SS + row) << 8) + (size_t)(h << 6) + d;
    *(float2*)&g_AO[base] = make_float2(__uint_as_float(f2tf(a0 * inv)),
                                        __uint_as_float(f2tf(a1 * inv)));
}

extern "C" void kernel_launch(void* const* d_in, const int* in_sizes, int n_in,
                              void* d_out, int out_size) {
    const float* q_in  = (const float*)d_in[0];
    const float* kv_in = (const float*)d_in[1];
    const float* Wq    = (const float*)d_in[3];
    const float* Wk    = (const float*)d_in[4];
    const float* Wv    = (const float*)d_in[5];
    const float* Wo    = (const float*)d_in[6];
    float* out = (float*)d_out;

    float *pQ, *pK, *pV, *pAO;
    cudaGetSymbolAddress((void**)&pQ,  g_Q);
    cudaGetSymbolAddress((void**)&pK,  g_K);
    cudaGetSymbolAddress((void**)&pV,  g_V);
    cudaGetSymbolAddress((void**)&pAO, g_AO);

    cudaFuncSetAttribute(attn_part_kernel,
                         cudaFuncAttributeMaxDynamicSharedMemorySize, ATTN_SMEM);

    prep_kernel<<<dim3((INDIM * NKV + 255) / 256, 2), 256>>>(Wq, Wk, Wv, Wo);

    dim3 gqkv(NKV / 128, (BB * SS) / 128, 3);   // (2, 32, 3)
    qkv_gemm_kernel<<<gqkv, 256>>>(q_in, kv_in, pQ, pK, pV);

    attn_part_kernel<<<dim3((SS / 64) * NSPLIT, BB * KVH_), 128, ATTN_SMEM>>>();
    attn_merge_kernel<<<(BB * KVH_ * SS) / 8, 256>>>();

    out_gemm_kernel<<<dim3(INDIM / 128, (BB * SS) / 128), 256>>>(pAO, out);
}

// round 13
// speedup vs baseline: 1.0671x; 1.0671x over previous
#include <cuda_runtime.h>
#include <math.h>

#define BB      2
#define SS      2048
#define INDIM   1024
#define QH_     16
#define KVH_    4
#define HD_     64
#define G_      4
#define NKV     256
#define QSCALE  0.180336879f   // 0.125 * log2(e)
#define NSPLIT  8

// permute within 8-group: w -> (w%4)*2 + w/4 ; position pair (2q,2q+1) holds (q, q+4)
#define PERM8(x) (((x) & ~7) | (((x) & 3) << 1) | ((((x) >> 2) & 1)))

__device__ float g_Wqs[INDIM * NKV];          // folded + scaled + tf32
__device__ float g_Wk[INDIM * NKV];           // tf32
__device__ float g_Wv[INDIM * NKV];           // tf32
__device__ float g_Wo[NKV * INDIM];           // tf32
__device__ float g_Q[BB * KVH_ * SS * HD_];   // tf32, pre-scaled, d-permuted
__device__ float g_K[BB * KVH_ * SS * HD_];   // tf32, d-permuted
__device__ float g_V[BB * KVH_ * HD_ * SS];   // tf32, TRANSPOSED [d][s], s-permuted
__device__ float g_AO[BB * SS * NKV];         // tf32 (merge output)
__device__ float  g_Op[BB * KVH_ * SS * NSPLIT * HD_];
__device__ float2 g_Ml[BB * KVH_ * SS * NSPLIT];

// --------------------------- helpers --------------------------------------
__device__ __forceinline__ unsigned f2tf(float f) {
    unsigned r;
    asm("cvt.rna.tf32.f32 %0, %1;" : "=r"(r) : "f"(f));
    return r;
}
__device__ __forceinline__ float ex2f(float x) {
    float y;
    asm("ex2.approx.f32 %0, %1;" : "=f"(y) : "f"(x));
    return y;
}
__device__ __forceinline__ void mma_tf32(float (&d)[4], const unsigned (&a)[4],
                                         const unsigned (&b)[2]) {
    asm volatile(
        "mma.sync.aligned.m16n8k8.row.col.f32.tf32.tf32.f32 "
        "{%0,%1,%2,%3}, {%4,%5,%6,%7}, {%8,%9}, {%0,%1,%2,%3};"
        : "+f"(d[0]), "+f"(d[1]), "+f"(d[2]), "+f"(d[3])
        : "r"(a[0]), "r"(a[1]), "r"(a[2]), "r"(a[3]), "r"(b[0]), "r"(b[1]));
}
__device__ __forceinline__ void cpa16(void* dst, const void* src) {
    unsigned d = (unsigned)__cvta_generic_to_shared(dst);
    asm volatile("cp.async.cg.shared.global [%0], [%1], 16;" :: "r"(d), "l"(src) : "memory");
}
#define CP_COMMIT() asm volatile("cp.async.commit_group;" ::: "memory")
#define CP_WAIT0()  asm volatile("cp.async.wait_group 0;" ::: "memory")
#define CP_WAIT1()  asm volatile("cp.async.wait_group 1;" ::: "memory")

// ---------------------------------------------------------------------------
// Fused prep: y=0 folds Wq (group-sum, scale, tf32); y=1 rounds Wk/Wv/Wo.
// ---------------------------------------------------------------------------
__global__ void prep_kernel(const float* __restrict__ Wq,
                            const float* __restrict__ Wk,
                            const float* __restrict__ Wv,
                            const float* __restrict__ Wo) {
    int idx = blockIdx.x * blockDim.x + threadIdx.x;
    if (blockIdx.y == 0) {
        if (idx >= INDIM * NKV) return;
        int i = idx >> 8;
        int n = idx & 255;
        int h = n >> 6, d = n & 63;
        const float* p = Wq + (size_t)i * (QH_ * HD_) + (size_t)(h * G_) * HD_ + d;
        g_Wqs[idx] = __uint_as_float(
            f2tf(QSCALE * (p[0] + p[HD_] + p[2 * HD_] + p[3 * HD_])));
    } else {
        const int Q4 = (INDIM * NKV) / 4;
        if (idx >= 3 * Q4) return;
        int which = idx / Q4;
        int off = (idx - which * Q4) * 4;
        const float* src = (which == 0) ? Wk : ((which == 1) ? Wv : Wo);
        float* dst = (which == 0) ? g_Wk : ((which == 1) ? g_Wv : g_Wo);
        float4 v = *(const float4*)(src + off);
        v.x = __uint_as_float(f2tf(v.x));
        v.y = __uint_as_float(f2tf(v.y));
        v.z = __uint_as_float(f2tf(v.z));
        v.w = __uint_as_float(f2tf(v.w));
        *(float4*)(dst + off) = v;
    }
}

// ---------------------------------------------------------------------------
// tf32 GEMM (R11 config: 128x64 tile, BK=16, 256 thr, 8 warps 4m x 2n,
// warp tile 32x32, 2-stage cp.async). SCAT: 0=plain, 1=Q/K (d-permuted
// [b][h][s][perm(d)]), 2=V (transposed [b][h][d][perm(s)]).
// ---------------------------------------------------------------------------
template<int KD, int N, int SCAT, bool CVT_A>
__device__ __forceinline__ void gemm_body(
        const float* __restrict__ A, const float* __restrict__ Bm,
        float* __restrict__ C) {
    __shared__ float As[2][128][20];
    __shared__ float Bs[2][16][72];

    int tid = threadIdx.x;
    int w = tid >> 5, lane = tid & 31, g = lane >> 2, qd = lane & 3;
    int wm = w & 3, wn = w >> 2;
    int m0 = blockIdx.y * 128, n0 = blockIdx.x * 64;

    int ar = tid >> 1, ac = (tid & 1) * 8;
    int br = tid >> 4, bc = (tid & 15) * 4;
    const float* ApG = A + (size_t)(m0 + ar) * KD + ac;
    const float* BpG = Bm + (size_t)br * N + n0 + bc;

    float acc[2][4][4];
    #pragma unroll
    for (int mt = 0; mt < 2; mt++)
        #pragma unroll
        for (int nt = 0; nt < 4; nt++)
            #pragma unroll
            for (int e = 0; e < 4; e++) acc[mt][nt][e] = 0.f;

    cpa16(&As[0][ar][ac],     ApG);
    cpa16(&As[0][ar][ac + 4], ApG + 4);
    cpa16(&Bs[0][br][bc],     BpG);
    CP_COMMIT();

    const int KT = KD / 16;
    int buf = 0;
    #pragma unroll 1
    for (int t = 0; t < KT; t++) {
        if (t + 1 < KT) {
            int k0 = (t + 1) * 16;
            cpa16(&As[buf ^ 1][ar][ac],     ApG + k0);
            cpa16(&As[buf ^ 1][ar][ac + 4], ApG + k0 + 4);
            cpa16(&Bs[buf ^ 1][br][bc],     BpG + (size_t)k0 * N);
            CP_COMMIT();
            CP_WAIT1();
        } else {
            CP_WAIT0();
        }
        __syncthreads();

        #pragma unroll
        for (int ks = 0; ks < 2; ks++) {
            int kb = ks * 8;
            unsigned af[2][4];
            #pragma unroll
            for (int mt = 0; mt < 2; mt++) {
                int row = wm * 32 + mt * 16 + g;
                if (CVT_A) {
                    af[mt][0] = f2tf(As[buf][row][kb + qd]);
                    af[mt][1] = f2tf(As[buf][row + 8][kb + qd]);
                    af[mt][2] = f2tf(As[buf][row][kb + qd + 4]);
                    af[mt][3] = f2tf(As[buf][row + 8][kb + qd + 4]);
                } else {
                    af[mt][0] = __float_as_uint(As[buf][row][kb + qd]);
                    af[mt][1] = __float_as_uint(As[buf][row + 8][kb + qd]);
                    af[mt][2] = __float_as_uint(As[buf][row][kb + qd + 4]);
                    af[mt][3] = __float_as_uint(As[buf][row + 8][kb + qd + 4]);
                }
            }
            unsigned bf[4][2];
            #pragma unroll
            for (int nt = 0; nt < 4; nt++) {
                int col = wn * 32 + nt * 8 + g;
                bf[nt][0] = __float_as_uint(Bs[buf][kb + qd][col]);
                bf[nt][1] = __float_as_uint(Bs[buf][kb + qd + 4][col]);
            }
            #pragma unroll
            for (int mt = 0; mt < 2; mt++)
                #pragma unroll
                for (int nt = 0; nt < 4; nt++)
                    mma_tf32(acc[mt][nt], af[mt], bf[nt]);
        }
        __syncthreads();
        buf ^= 1;
    }

    #pragma unroll
    for (int mt = 0; mt < 2; mt++) {
        #pragma unroll
        for (int nt = 0; nt < 4; nt++) {
            int row = m0 + wm * 32 + mt * 16 + g;
            int col = n0 + wn * 32 + nt * 8 + 2 * qd;
            if (SCAT == 0) {
                *(float2*)&C[(size_t)row * N + col] =
                    make_float2(acc[mt][nt][0], acc[mt][nt][1]);
                *(float2*)&C[(size_t)(row + 8) * N + col] =
                    make_float2(acc[mt][nt][2], acc[mt][nt][3]);
            } else {
                float v0 = __uint_as_float(f2tf(acc[mt][nt][0]));
                float v1 = __uint_as_float(f2tf(acc[mt][nt][1]));
                float v2 = __uint_as_float(f2tf(acc[mt][nt][2]));
                float v3 = __uint_as_float(f2tf(acc[mt][nt][3]));
                int b = row >> 11, s = row & 2047;
                int h = col >> 6, dd = col & 63;
                if (SCAT == 1) {
                    // [b][h][s][perm(d)]
                    size_t base = (((size_t)(b * KVH_ + h) * SS + s) << 6);
                    int dp0 = PERM8(dd), dp1 = PERM8(dd + 1);
                    C[base + dp0] = v0;
                    C[base + dp1] = v1;
                    C[base + 512 + dp0] = v2;   // s+8 -> +8*64
                    C[base + 512 + dp1] = v3;
                } else {
                    // V transposed: [b][h][d][perm(s)]
                    size_t r0a = ((size_t)((b * KVH_ + h) * HD_ + dd)) * SS;
                    int sp = PERM8(s);          // PERM8(s+8) == sp+8
                    C[r0a + sp]          = v0;
                    C[r0a + SS + sp]     = v1;  // dd+1
                    C[r0a + sp + 8]      = v2;
                    C[r0a + SS + sp + 8] = v3;
                }
            }
        }
    }
}

__global__ void __launch_bounds__(256) qkv_gemm_kernel(
        const float* __restrict__ q_in, const float* __restrict__ kv_in,
        float* __restrict__ Q, float* __restrict__ K, float* __restrict__ V) {
    int z = blockIdx.z;
    if (z == 0)      gemm_body<INDIM, NKV, 1, true>(q_in,  g_Wqs, Q);
    else if (z == 1) gemm_body<INDIM, NKV, 1, true>(kv_in, g_Wk,  K);
    else             gemm_body<INDIM, NKV, 2, true>(kv_in, g_Wv,  V);
}

__global__ void __launch_bounds__(256) out_gemm_kernel(
        const float* __restrict__ A, float* __restrict__ C) {
    gemm_body<NKV, INDIM, 0, false>(A, g_Wo, C);
}

// ---------------------------------------------------------------------------
// Causal flash attention, split-KV (NSPLIT=8). LDS.64 fragment loads:
// Q/K are d-permuted; V is [d][perm(s)] transposed. Pitch 72 (mod 32 == 8)
// makes uint2 loads phase-conflict-free.
// ---------------------------------------------------------------------------
#define KP 72
#define VP 72
#define ATTN_SMEM ((2 * 64 * KP + 2 * 64 * VP) * 4)

__global__ void __launch_bounds__(128, 3) attn_part_kernel() {
    extern __shared__ unsigned smp[];
    unsigned* Kb0 = smp;
    unsigned* Kb1 = Kb0 + 64 * KP;
    unsigned* Vb0 = Kb1 + 64 * KP;
    unsigned* Vb1 = Vb0 + 64 * VP;

    int bh = blockIdx.y;
    int qidx = blockIdx.x / NSPLIT;
    int split = blockIdx.x % NSPLIT;
    int qt = (SS / 64 - 1) - qidx;
    int q0 = qt * 64;
    int nseg = qt + 1;
    int lo = (split * nseg) / NSPLIT;
    int hi = ((split + 1) * nseg) / NSPLIT;

    const float* Qh = g_Q + (size_t)bh * SS * HD_;
    const float* Kh = g_K + (size_t)bh * SS * HD_;
    const float* Vh = g_V + (size_t)bh * HD_ * SS;   // [d][s]

    int tid = threadIdx.x;
    int w = tid >> 5, lane = tid & 31, g = lane >> 2, qd = lane & 3;
    int r0 = w * 16 + g;
    int lr = tid >> 4, lc = tid & 15;

    int sl0 = (lane & 28) | (qd >> 1);
    int sl1 = sl0 + 2;
    bool odd = (qd & 1) != 0;

    float m0 = -3.0e38f, m1 = -3.0e38f, l0 = 0.f, l1 = 0.f;
    float oacc[8][4];
    #pragma unroll
    for (int dt = 0; dt < 8; dt++)
        #pragma unroll
        for (int e = 0; e < 4; e++) oacc[dt][e] = 0.f;

    unsigned qf[8][4];

    if (lo < hi) {
        // stage Q (raw copy; d-permuted in memory)
        {
            const uint4* Qsrc = (const uint4*)(Qh + (size_t)q0 * 64);
            #pragma unroll
            for (int it = 0; it < 8; it++) {
                int r = lr + it * 8;
                *(uint4*)&Kb0[r * KP + lc * 4] = Qsrc[r * 16 + lc];
            }
        }
        __syncthreads();
        #pragma unroll
        for (int ks = 0; ks < 8; ks++) {
            uint2 qa = *(uint2*)&Kb0[r0 * KP + ks * 8 + 2 * qd];
            uint2 qb = *(uint2*)&Kb0[(r0 + 8) * KP + ks * 8 + 2 * qd];
            qf[ks][0] = qa.x; qf[ks][1] = qb.x;
            qf[ks][2] = qa.y; qf[ks][3] = qb.y;
        }
        __syncthreads();

        // prologue: tile lo
        {
            unsigned* Kn = (lo & 1) ? Kb1 : Kb0;
            unsigned* Vn = (lo & 1) ? Vb1 : Vb0;
            const float* Ksrc = Kh + (size_t)lo * 4096;
            const float* Vsrc = Vh + (size_t)lo * 64;
            #pragma unroll
            for (int it = 0; it < 8; it++) {
                int r = lr + it * 8;
                cpa16(&Kn[r * KP + lc * 4], Ksrc + r * 64 + lc * 4);
                cpa16(&Vn[r * VP + lc * 4], Vsrc + (size_t)r * SS + lc * 4);
            }
        }
        CP_COMMIT();

        #pragma unroll 1
        for (int kt = lo; kt < hi; kt++) {
            unsigned* Kc = (kt & 1) ? Kb1 : Kb0;
            unsigned* Vc = (kt & 1) ? Vb1 : Vb0;
            if (kt + 1 < hi) {
                unsigned* Kn = (kt & 1) ? Kb0 : Kb1;
                unsigned* Vn = (kt & 1) ? Vb0 : Vb1;
                const float* Ksrc = Kh + (size_t)(kt + 1) * 4096;
                const float* Vsrc = Vh + (size_t)(kt + 1) * 64;
                #pragma unroll
                for (int it = 0; it < 8; it++) {
                    int r = lr + it * 8;
                    cpa16(&Kn[r * KP + lc * 4], Ksrc + r * 64 + lc * 4);
                    cpa16(&Vn[r * VP + lc * 4], Vsrc + (size_t)r * SS + lc * 4);
                }
                CP_COMMIT();
                CP_WAIT1();
            } else {
                CP_WAIT0();
            }
            __syncthreads();

            // --- S = Q K^T (LDS.64 B-frags) ---
            float sacc[8][4];
            #pragma unroll
            for (int nt = 0; nt < 8; nt++)
                #pragma unroll
                for (int e = 0; e < 4; e++) sacc[nt][e] = 0.f;
            #pragma unroll
            for (int nt = 0; nt < 8; nt++) {
                #pragma unroll
                for (int ks = 0; ks < 8; ks++) {
                    uint2 kk = *(uint2*)&Kc[(nt * 8 + g) * KP + ks * 8 + 2 * qd];
                    unsigned kb[2] = {kk.x, kk.y};
                    mma_tf32(sacc[nt], qf[ks], kb);
                }
            }

            if (kt == qt) {
                int grow0 = q0 + r0;
                #pragma unroll
                for (int nt = 0; nt < 8; nt++) {
                    int col = kt * 64 + nt * 8 + 2 * qd;
                    if (col     > grow0)     sacc[nt][0] = -1.0e30f;
                    if (col + 1 > grow0)     sacc[nt][1] = -1.0e30f;
                    if (col     > grow0 + 8) sacc[nt][2] = -1.0e30f;
                    if (col + 1 > grow0 + 8) sacc[nt][3] = -1.0e30f;
                }
            }

            // --- online softmax (exp2 domain) ---
            float mx0 = -3.0e38f, mx1 = -3.0e38f;
            #pragma unroll
            for (int nt = 0; nt < 8; nt++) {
                mx0 = fmaxf(mx0, fmaxf(sacc[nt][0], sacc[nt][1]));
                mx1 = fmaxf(mx1, fmaxf(sacc[nt][2], sacc[nt][3]));
            }
            mx0 = fmaxf(mx0, __shfl_xor_sync(0xffffffffu, mx0, 1));
            mx0 = fmaxf(mx0, __shfl_xor_sync(0xffffffffu, mx0, 2));
            mx1 = fmaxf(mx1, __shfl_xor_sync(0xffffffffu, mx1, 1));
            mx1 = fmaxf(mx1, __shfl_xor_sync(0xffffffffu, mx1, 2));
            float mn0 = fmaxf(m0, mx0), mn1 = fmaxf(m1, mx1);
            float c0 = ex2f(m0 - mn0), c1 = ex2f(m1 - mn1);
            m0 = mn0; m1 = mn1;
            float rs0 = 0.f, rs1 = 0.f;
            #pragma unroll
            for (int nt = 0; nt < 8; nt++) {
                float p0 = ex2f(sacc[nt][0] - mn0);
                float p1 = ex2f(sacc[nt][1] - mn0);
                float p2 = ex2f(sacc[nt][2] - mn1);
                float p3 = ex2f(sacc[nt][3] - mn1);
                sacc[nt][0] = p0; sacc[nt][1] = p1;
                sacc[nt][2] = p2; sacc[nt][3] = p3;
                rs0 += p0 + p1; rs1 += p2 + p3;
            }
            rs0 += __shfl_xor_sync(0xffffffffu, rs0, 1);
            rs0 += __shfl_xor_sync(0xffffffffu, rs0, 2);
            rs1 += __shfl_xor_sync(0xffffffffu, rs1, 1);
            rs1 += __shfl_xor_sync(0xffffffffu, rs1, 2);
            l0 = l0 * c0 + rs0;
            l1 = l1 * c1 + rs1;
            #pragma unroll
            for (int dt = 0; dt < 8; dt++) {
                oacc[dt][0] *= c0; oacc[dt][1] *= c0;
                oacc[dt][2] *= c1; oacc[dt][3] *= c1;
            }

            // --- P transpose via quad shuffles (verified) ---
            unsigned pa[8][4];
            #pragma unroll
            for (int ks = 0; ks < 8; ks++) {
                float a0 = __shfl_sync(0xffffffffu, sacc[ks][0], sl0);
                float a1 = __shfl_sync(0xffffffffu, sacc[ks][1], sl0);
                float b0 = __shfl_sync(0xffffffffu, sacc[ks][2], sl0);
                float b1 = __shfl_sync(0xffffffffu, sacc[ks][3], sl0);
                float e0 = __shfl_sync(0xffffffffu, sacc[ks][0], sl1);
                float e1 = __shfl_sync(0xffffffffu, sacc[ks][1], sl1);
                float f0 = __shfl_sync(0xffffffffu, sacc[ks][2], sl1);
                float f1 = __shfl_sync(0xffffffffu, sacc[ks][3], sl1);
                pa[ks][0] = f2tf(odd ? a1 : a0);
                pa[ks][1] = f2tf(odd ? b1 : b0);
                pa[ks][2] = f2tf(odd ? e1 : e0);
                pa[ks][3] = f2tf(odd ? f1 : f0);
            }

            // --- O += P V (V^T smem, LDS.64 over permuted keys) ---
            #pragma unroll
            for (int dt = 0; dt < 8; dt++) {
                #pragma unroll
                for (int ks = 0; ks < 8; ks++) {
                    uint2 vv = *(uint2*)&Vc[(dt * 8 + g) * VP + ks * 8 + 2 * qd];
                    unsigned vb[2] = {vv.x, vv.y};
                    mma_tf32(oacc[dt], pa[ks], vb);
                }
            }
            __syncthreads();
        }
    }

    int grow = q0 + r0;
    size_t rid0 = ((size_t)bh * SS + grow) * NSPLIT + split;
    size_t rid1 = ((size_t)bh * SS + grow + 8) * NSPLIT + split;
    #pragma unroll
    for (int dt = 0; dt < 8; dt++) {
        int d = dt * 8 + 2 * qd;
        *(float2*)&g_Op[(rid0 << 6) + d] = make_float2(oacc[dt][0], oacc[dt][1]);
        *(float2*)&g_Op[(rid1 << 6) + d] = make_float2(oacc[dt][2], oacc[dt][3]);
    }
    if (qd == 0) {
        g_Ml[rid0] = make_float2(m0, l0);
        g_Ml[rid1] = make_float2(m1, l1);
    }
}

// ---------------------------------------------------------------------------
// Merge partials; emits tf32-rounded g_AO so out_gemm skips all cvts.
// ---------------------------------------------------------------------------
__global__ void __launch_bounds__(256) attn_merge_kernel() {
    int gr = blockIdx.x * 8 + (threadIdx.x >> 5);
    int lane = threadIdx.x & 31;
    int bh = gr >> 11;
    int row = gr & 2047;
    int b = bh >> 2, h = bh & 3;

    float2 ml[NSPLIT];
    #pragma unroll
    for (int s = 0; s < NSPLIT; s++) ml[s] = g_Ml[(size_t)gr * NSPLIT + s];
    float mmax = -3.0e38f;
    #pragma unroll
    for (int s = 0; s < NSPLIT; s++) mmax = fmaxf(mmax, ml[s].x);
    float ws[NSPLIT];
    float lt = 0.f;
    #pragma unroll
    for (int s = 0; s < NSPLIT; s++) {
        ws[s] = ex2f(ml[s].x - mmax);
        lt += ml[s].y * ws[s];
    }
    float inv = 1.0f / lt;

    int d = lane * 2;
    float a0 = 0.f, a1 = 0.f;
    #pragma unroll
    for (int s = 0; s < NSPLIT; s++) {
        float2 o = *(const float2*)&g_Op[((((size_t)gr * NSPLIT) + s) << 6) + d];
        a0 += o.x * ws[s];
        a1 += o.y * ws[s];
    }
    size_t base = (((size_t)b * SS + row) << 8) + (size_t)(h << 6) + d;
    *(float2*)&g_AO[base] = make_float2(__uint_as_float(f2tf(a0 * inv)),
                                        __uint_as_float(f2tf(a1 * inv)));
}

extern "C" void kernel_launch(void* const* d_in, const int* in_sizes, int n_in,
                              void* d_out, int out_size) {
    const float* q_in  = (const float*)d_in[0];
    const float* kv_in = (const float*)d_in[1];
    const float* Wq    = (const float*)d_in[3];
    const float* Wk    = (const float*)d_in[4];
    const float* Wv    = (const float*)d_in[5];
    const float* Wo    = (const float*)d_in[6];
    float* out = (float*)d_out;

    float *pQ, *pK, *pV, *pAO;
    cudaGetSymbolAddress((void**)&pQ,  g_Q);
    cudaGetSymbolAddress((void**)&pK,  g_K);
    cudaGetSymbolAddress((void**)&pV,  g_V);
    cudaGetSymbolAddress((void**)&pAO, g_AO);

    cudaFuncSetAttribute(attn_part_kernel,
                         cudaFuncAttributeMaxDynamicSharedMemorySize, ATTN_SMEM);

    prep_kernel<<<dim3((INDIM * NKV + 255) / 256, 2), 256>>>(Wq, Wk, Wv, Wo);

    dim3 gqkv(NKV / 64, (BB * SS) / 128, 3);   // (4, 32, 3)
    qkv_gemm_kernel<<<gqkv, 256>>>(q_in, kv_in, pQ, pK, pV);

    attn_part_kernel<<<dim3((SS / 64) * NSPLIT, BB * KVH_), 128, ATTN_SMEM>>>();
    attn_merge_kernel<<<(BB * KVH_ * SS) / 8, 256>>>();

    out_gemm_kernel<<<dim3(INDIM / 64, (BB * SS) / 128), 256>>>(pAO, out);
}